// round 1
// baseline (speedup 1.0000x reference)
#include <cuda_runtime.h>

#define NN 250000
#define EE 2500000
#define GG 2048
#define KK 30
#define HD 32

// -------- scratch (static device globals; no runtime allocation) --------
__device__ int   g_degcnt[NN];
__device__ float g_dis[NN];
__device__ float g_c[EE];
__device__ int   g_start[GG + 1];
__device__ float g_bufA[(size_t)NN * HD];
__device__ float g_bufB[(size_t)NN * HD];
__device__ float g_bufC[(size_t)NN * HD];
__device__ float g_pool[(size_t)GG * KK * HD];

// -------- degree / normalization --------
__global__ void k_zero_deg() {
    int i = blockIdx.x * blockDim.x + threadIdx.x;
    if (i < NN) g_degcnt[i] = 0;
}

__global__ void k_count(const int* __restrict__ dst) {
    int e = blockIdx.x * blockDim.x + threadIdx.x;
    if (e < EE) atomicAdd(&g_degcnt[dst[e]], 1);
}

__global__ void k_dis() {
    int i = blockIdx.x * blockDim.x + threadIdx.x;
    if (i < NN) g_dis[i] = rsqrtf((float)g_degcnt[i] + 1.0f);
}

__global__ void k_coef(const int* __restrict__ src, const int* __restrict__ dst) {
    int e = blockIdx.x * blockDim.x + threadIdx.x;
    if (e < EE) g_c[e] = g_dis[src[e]] * g_dis[dst[e]];
}

// starts[g] = first index i with batch[i] >= g (batch is sorted ascending)
__global__ void k_starts(const int* __restrict__ batch) {
    int g = blockIdx.x * blockDim.x + threadIdx.x;
    if (g > GG) return;
    int lo = 0, hi = NN;
    while (lo < hi) {
        int mid = (lo + hi) >> 1;
        if (batch[mid] < g) lo = mid + 1; else hi = mid;
    }
    g_start[g] = lo;
}

// -------- per-node dense transform: Hlin = X @ W ; Agg = Hlin * dis^2 --------
template <int IN>
__global__ void k_mm(const float* __restrict__ X, const float* __restrict__ W,
                     float* __restrict__ Hlin, float* __restrict__ Agg) {
    __shared__ float sW[IN * HD];
    for (int i = threadIdx.x; i < IN * HD; i += blockDim.x) sW[i] = W[i];
    __syncthreads();
    int node = blockIdx.x * blockDim.x + threadIdx.x;
    if (node >= NN) return;
    float xin[IN];
#pragma unroll
    for (int k = 0; k < IN; k++) xin[k] = X[(size_t)node * IN + k];
    float d = g_dis[node];
    float d2 = d * d;
    float out[HD];
#pragma unroll
    for (int f = 0; f < HD; f++) {
        float acc = 0.f;
#pragma unroll
        for (int k = 0; k < IN; k++) acc = fmaf(xin[k], sW[k * HD + f], acc);
        out[f] = acc;
    }
    float4* ph = (float4*)(Hlin + (size_t)node * HD);
    float4* pa = (float4*)(Agg + (size_t)node * HD);
#pragma unroll
    for (int q = 0; q < HD / 4; q++) {
        float4 v = ((float4*)out)[q];
        ph[q] = v;
        pa[q] = make_float4(v.x * d2, v.y * d2, v.z * d2, v.w * d2);
    }
}

// -------- edge scatter: Agg[dst] += Hlin[src] * c[e]   (8 threads / edge) --------
__global__ void k_edge(const int* __restrict__ src, const int* __restrict__ dst,
                       const float* __restrict__ Hlin, float* __restrict__ Agg) {
    int gid = blockIdx.x * blockDim.x + threadIdx.x;
    int e = gid >> 3;
    if (e >= EE) return;
    int part = gid & 7;
    int s = src[e];
    int d = dst[e];
    float cc = g_c[e];
    const float4 v = *(const float4*)(Hlin + (size_t)s * HD + part * 4);
    float* p = Agg + (size_t)d * HD + part * 4;
    asm volatile("red.global.add.v4.f32 [%0], {%1,%2,%3,%4};"
                 :: "l"(p), "f"(v.x * cc), "f"(v.y * cc), "f"(v.z * cc), "f"(v.w * cc)
                 : "memory");
}

// -------- finalize: Agg = relu(Agg + b) --------
__global__ void k_fin(float* __restrict__ Agg, const float* __restrict__ b) {
    int i = blockIdx.x * blockDim.x + threadIdx.x;
    if (i < NN * HD) Agg[i] = fmaxf(Agg[i] + b[i & (HD - 1)], 0.f);
}

// -------- sort pooling: top-30 per graph by H[:,31] desc, stable by index --------
#define MAXC 1024
__global__ void k_sortpool(const float* __restrict__ H) {
    int g = blockIdx.x;
    int s = g_start[g];
    int cnt = g_start[g + 1] - s;
    __shared__ float keys[MAXC];
    bool sh = (cnt <= MAXC);
    if (sh)
        for (int i = threadIdx.x; i < cnt; i += blockDim.x)
            keys[i] = H[(size_t)(s + i) * HD + 31];
    for (int i = threadIdx.x; i < KK * HD; i += blockDim.x)
        g_pool[(size_t)g * KK * HD + i] = 0.f;
    __syncthreads();
    for (int i = threadIdx.x; i < cnt; i += blockDim.x) {
        float ki = sh ? keys[i] : H[(size_t)(s + i) * HD + 31];
        int r = 0;
        for (int j = 0; j < cnt; j++) {
            float kj = sh ? keys[j] : H[(size_t)(s + j) * HD + 31];
            r += (kj > ki) || (kj == ki && j < i);
            if (r >= KK) break;
        }
        if (r < KK) {
            const float4* sp = (const float4*)(H + (size_t)(s + i) * HD);
            float4* dp = (float4*)(g_pool + (size_t)g * KK * HD + r * HD);
#pragma unroll
            for (int q = 0; q < HD / 4; q++) dp[q] = sp[q];
        }
    }
}

// -------- head: conv1(32->16,w5) relu, conv2(16->32,w5) relu, fc(704->128) relu, fc(128->1) --------
__global__ void k_head(const float* __restrict__ cw1, const float* __restrict__ cb1,
                       const float* __restrict__ cw2, const float* __restrict__ cb2,
                       const float* __restrict__ lw1, const float* __restrict__ lb1,
                       const float* __restrict__ lw2, const float* __restrict__ lb2,
                       float* __restrict__ out) {
    int g = blockIdx.x;
    int tid = threadIdx.x;  // 128 threads
    __shared__ float sP[KK * HD];       // 960  : pooled, [t][c]
    __shared__ float sw1[16 * HD * 5];  // 2560
    __shared__ float sw2[32 * 16 * 5];  // 2560
    __shared__ float sC1[16 * 26];
    __shared__ float sC2[32 * 22];
    __shared__ float sred[128];

    for (int i = tid; i < KK * HD; i += 128) sP[i] = g_pool[(size_t)g * KK * HD + i];
    for (int i = tid; i < 16 * HD * 5; i += 128) sw1[i] = cw1[i];
    for (int i = tid; i < 32 * 16 * 5; i += 128) sw2[i] = cw2[i];
    __syncthreads();

    // conv1: y[o][t] = relu(sum_{c,j} P[t+j][c] * cw1[o][c][j] + cb1[o])
    for (int idx = tid; idx < 16 * 26; idx += 128) {
        int o = idx / 26, t = idx % 26;
        float acc = cb1[o];
#pragma unroll
        for (int j = 0; j < 5; j++)
#pragma unroll
            for (int c = 0; c < HD; c++)
                acc = fmaf(sP[(t + j) * HD + c], sw1[o * 160 + c * 5 + j], acc);
        sC1[o * 26 + t] = fmaxf(acc, 0.f);
    }
    __syncthreads();

    // conv2: y[o][t] = relu(sum_{c,j} C1[c][t+j] * cw2[o][c][j] + cb2[o])
    for (int idx = tid; idx < 32 * 22; idx += 128) {
        int o = idx / 22, t = idx % 22;
        float acc = cb2[o];
#pragma unroll
        for (int c = 0; c < 16; c++)
#pragma unroll
            for (int j = 0; j < 5; j++)
                acc = fmaf(sC1[c * 26 + t + j], sw2[o * 80 + c * 5 + j], acc);
        sC2[o * 22 + t] = fmaxf(acc, 0.f);
    }
    __syncthreads();

    // fc1 (704 -> 128), each thread = one output j; then fc2 (128 -> 1) reduce
    float acc = lb1[tid];
    for (int i = 0; i < 704; i++)
        acc = fmaf(sC2[i], lw1[i * 128 + tid], acc);
    acc = fmaxf(acc, 0.f);
    sred[tid] = acc * lw2[tid];
    __syncthreads();
    for (int s2 = 64; s2 > 0; s2 >>= 1) {
        if (tid < s2) sred[tid] += sred[tid + s2];
        __syncthreads();
    }
    if (tid == 0) out[g] = sred[0] + lb2[0];
}

// -------- launch --------
extern "C" void kernel_launch(void* const* d_in, const int* in_sizes, int n_in,
                              void* d_out, int out_size) {
    const float* x = (const float*)d_in[0];
    const int* ei = (const int*)d_in[1];
    const int* batch = (const int*)d_in[2];
    // num_graphs may or may not be materialized as a size-1 buffer
    int wi = 3;
    if (n_in > 3 && in_sizes[3] == 1) wi = 4;
    const float* W1  = (const float*)d_in[wi + 0];
    const float* b1  = (const float*)d_in[wi + 1];
    const float* W2  = (const float*)d_in[wi + 2];
    const float* b2  = (const float*)d_in[wi + 3];
    const float* W3  = (const float*)d_in[wi + 4];
    const float* b3  = (const float*)d_in[wi + 5];
    const float* cw1 = (const float*)d_in[wi + 6];
    const float* cb1 = (const float*)d_in[wi + 7];
    const float* cw2 = (const float*)d_in[wi + 8];
    const float* cb2 = (const float*)d_in[wi + 9];
    const float* lw1 = (const float*)d_in[wi + 10];
    const float* lb1 = (const float*)d_in[wi + 11];
    const float* lw2 = (const float*)d_in[wi + 12];
    const float* lb2 = (const float*)d_in[wi + 13];
    float* out = (float*)d_out;
    const int* src = ei;
    const int* dst = ei + EE;

    float *pA, *pB, *pC;
    cudaGetSymbolAddress((void**)&pA, g_bufA);
    cudaGetSymbolAddress((void**)&pB, g_bufB);
    cudaGetSymbolAddress((void**)&pC, g_bufC);

    k_zero_deg<<<(NN + 255) / 256, 256>>>();
    k_count<<<(EE + 255) / 256, 256>>>(dst);
    k_dis<<<(NN + 255) / 256, 256>>>();
    k_coef<<<(EE + 255) / 256, 256>>>(src, dst);
    k_starts<<<(GG + 256) / 256, 256>>>(batch);

    // layer 1: X = x (N,9)
    k_mm<9><<<(NN + 255) / 256, 256>>>(x, W1, pB, pA);
    k_edge<<<(EE * 8 + 255) / 256, 256>>>(src, dst, pB, pA);
    k_fin<<<(NN * HD + 255) / 256, 256>>>(pA, b1);
    // layer 2: X = pA
    k_mm<32><<<(NN + 255) / 256, 256>>>(pA, W2, pB, pC);
    k_edge<<<(EE * 8 + 255) / 256, 256>>>(src, dst, pB, pC);
    k_fin<<<(NN * HD + 255) / 256, 256>>>(pC, b2);
    // layer 3: X = pC
    k_mm<32><<<(NN + 255) / 256, 256>>>(pC, W3, pB, pA);
    k_edge<<<(EE * 8 + 255) / 256, 256>>>(src, dst, pB, pA);
    k_fin<<<(NN * HD + 255) / 256, 256>>>(pA, b3);

    k_sortpool<<<GG, 128>>>(pA);
    k_head<<<GG, 128>>>(cw1, cb1, cw2, cb2, lw1, lb1, lw2, lb2, out);
}

// round 2
// speedup vs baseline: 1.2124x; 1.2124x over previous
#include <cuda_runtime.h>

#define NN 250000
#define EE 2500000
#define GG 2048
#define KK 30
#define HD 32

// -------- scratch (static device globals; no runtime allocation) --------
__device__ int   g_degcnt[NN];
__device__ float g_dis[NN];
__device__ int   g_nstart[NN];
__device__ int   g_cursor[NN];
__device__ int   g_total;
__device__ int2  g_csr[EE];          // (src, bitcast(dis[src]))
__device__ int   g_start[GG + 1];
__device__ float g_bufA[(size_t)NN * HD];
__device__ float g_bufB[(size_t)NN * HD];
__device__ float g_pool[(size_t)GG * KK * HD];
__device__ float g_feat[(size_t)GG * 704];

// -------- prologue --------
__global__ void k_init() {
    int i = blockIdx.x * blockDim.x + threadIdx.x;
    if (i < NN) g_degcnt[i] = 0;
    if (i == 0) g_total = 0;
}

__global__ void k_count(const int* __restrict__ dst) {
    int e = blockIdx.x * blockDim.x + threadIdx.x;
    if (e < EE) atomicAdd(&g_degcnt[dst[e]], 1);
}

__global__ void k_dis() {
    int i = blockIdx.x * blockDim.x + threadIdx.x;
    if (i < NN) g_dis[i] = rsqrtf((float)g_degcnt[i] + 1.0f);
}

// bump-allocate CSR buckets (bucket placement order is irrelevant to per-node math)
__global__ void k_alloc() {
    int i = blockIdx.x * blockDim.x + threadIdx.x;
    if (i < NN) {
        int deg = g_degcnt[i];
        int s = atomicAdd(&g_total, deg);
        g_nstart[i] = s;
        g_cursor[i] = s;
    }
}

__global__ void k_scatter(const int* __restrict__ src, const int* __restrict__ dst) {
    int e = blockIdx.x * blockDim.x + threadIdx.x;
    if (e < EE) {
        int d = dst[e];
        int s = src[e];
        int p = atomicAdd(&g_cursor[d], 1);
        g_csr[p] = make_int2(s, __float_as_int(g_dis[s]));
    }
}

// starts[g] = first index i with batch[i] >= g (batch sorted ascending)
__global__ void k_starts(const int* __restrict__ batch) {
    int g = blockIdx.x * blockDim.x + threadIdx.x;
    if (g > GG) return;
    int lo = 0, hi = NN;
    while (lo < hi) {
        int mid = (lo + hi) >> 1;
        if (batch[mid] < g) lo = mid + 1; else hi = mid;
    }
    g_start[g] = lo;
}

// -------- layer 1 dense: Hlin = X @ W  (IN=9) --------
template <int IN>
__global__ void k_mm(const float* __restrict__ X, const float* __restrict__ W,
                     float* __restrict__ Hlin) {
    __shared__ float sW[IN * HD];
    for (int i = threadIdx.x; i < IN * HD; i += blockDim.x) sW[i] = W[i];
    __syncthreads();
    int node = blockIdx.x * blockDim.x + threadIdx.x;
    if (node >= NN) return;
    float xin[IN];
#pragma unroll
    for (int k = 0; k < IN; k++) xin[k] = X[(size_t)node * IN + k];
    float out[HD];
#pragma unroll
    for (int f = 0; f < HD; f++) {
        float acc = 0.f;
#pragma unroll
        for (int k = 0; k < IN; k++) acc = fmaf(xin[k], sW[k * HD + f], acc);
        out[f] = acc;
    }
    float4* ph = (float4*)(Hlin + (size_t)node * HD);
#pragma unroll
    for (int q = 0; q < HD / 4; q++) ph[q] = ((float4*)out)[q];
}

// -------- fused CSR aggregate + bias + relu (+ optional next-layer GEMV) --------
// 8 threads per node, 32 nodes per 256-thread block.
template <bool NEXT>
__global__ void k_agg(const float* __restrict__ Hlin, const float* __restrict__ b,
                      const float* __restrict__ Wn, float* __restrict__ Out) {
    __shared__ float sW[HD * HD];   // next-layer weight
    __shared__ float sH[32 * 33];   // relu'd rows for GEMV
    int tid = threadIdx.x;
    if (NEXT)
        for (int i = tid; i < HD * HD; i += 256) sW[i] = Wn[i];
    int ln = tid >> 3, part = tid & 7;
    int node = blockIdx.x * 32 + ln;
    float h[4];
    if (node < NN) {
        float dd = g_dis[node];
        int s0 = g_nstart[node];
        int deg = g_degcnt[node];
        float4 acc = make_float4(0.f, 0.f, 0.f, 0.f);
        int2 ent = (deg > 0) ? g_csr[s0] : make_int2(0, 0);
        for (int e = 0; e < deg; e++) {
            int2 nxt = (e + 1 < deg) ? g_csr[s0 + e + 1] : ent;
            float dv = __int_as_float(ent.y);
            const float4 hv = *(const float4*)(Hlin + (size_t)ent.x * HD + part * 4);
            acc.x = fmaf(dv, hv.x, acc.x);
            acc.y = fmaf(dv, hv.y, acc.y);
            acc.z = fmaf(dv, hv.z, acc.z);
            acc.w = fmaf(dv, hv.w, acc.w);
            ent = nxt;
        }
        const float4 self = *(const float4*)(Hlin + (size_t)node * HD + part * 4);
        const float4 bb = *(const float4*)(b + part * 4);
        float d2 = dd * dd;
        h[0] = fmaxf(fmaf(dd, acc.x, fmaf(d2, self.x, bb.x)), 0.f);
        h[1] = fmaxf(fmaf(dd, acc.y, fmaf(d2, self.y, bb.y)), 0.f);
        h[2] = fmaxf(fmaf(dd, acc.z, fmaf(d2, self.z, bb.z)), 0.f);
        h[3] = fmaxf(fmaf(dd, acc.w, fmaf(d2, self.w, bb.w)), 0.f);
        if (!NEXT) {
            *(float4*)(Out + (size_t)node * HD + part * 4) = make_float4(h[0], h[1], h[2], h[3]);
        } else {
#pragma unroll
            for (int i = 0; i < 4; i++) sH[ln * 33 + part * 4 + i] = h[i];
        }
    }
    if (NEXT) {
        __syncthreads();
        if (node < NN) {
            float o[4] = {0.f, 0.f, 0.f, 0.f};
#pragma unroll 8
            for (int k = 0; k < HD; k++) {
                float hk = sH[ln * 33 + k];
#pragma unroll
                for (int i = 0; i < 4; i++) o[i] = fmaf(hk, sW[k * HD + part * 4 + i], o[i]);
            }
            *(float4*)(Out + (size_t)node * HD + part * 4) = make_float4(o[0], o[1], o[2], o[3]);
        }
    }
}

// -------- sort pooling: top-30 per graph by H[:,31] desc, stable by index --------
#define MAXC 1024
__global__ void k_sortpool(const float* __restrict__ H) {
    int g = blockIdx.x;
    int s = g_start[g];
    int cnt = g_start[g + 1] - s;
    __shared__ float keys[MAXC];
    bool sh = (cnt <= MAXC);
    if (sh)
        for (int i = threadIdx.x; i < cnt; i += blockDim.x)
            keys[i] = H[(size_t)(s + i) * HD + 31];
    for (int i = threadIdx.x; i < KK * HD; i += blockDim.x)
        g_pool[(size_t)g * KK * HD + i] = 0.f;
    __syncthreads();
    for (int i = threadIdx.x; i < cnt; i += blockDim.x) {
        float ki = sh ? keys[i] : H[(size_t)(s + i) * HD + 31];
        int r = 0;
        for (int j = 0; j < cnt; j++) {
            float kj = sh ? keys[j] : H[(size_t)(s + j) * HD + 31];
            r += (kj > ki) || (kj == ki && j < i);
            if (r >= KK) break;
        }
        if (r < KK) {
            const float4* sp = (const float4*)(H + (size_t)(s + i) * HD);
            float4* dp = (float4*)(g_pool + (size_t)g * KK * HD + r * HD);
#pragma unroll
            for (int q = 0; q < HD / 4; q++) dp[q] = sp[q];
        }
    }
}

// -------- conv head per graph: conv1(32->16,w5) relu, conv2(16->32,w5) relu -> g_feat --------
__global__ void k_conv(const float* __restrict__ cw1, const float* __restrict__ cb1,
                       const float* __restrict__ cw2, const float* __restrict__ cb2) {
    int g = blockIdx.x;
    int tid = threadIdx.x;  // 128 threads
    __shared__ float sP[KK * HD];
    __shared__ float sw1[16 * HD * 5];
    __shared__ float sw2[32 * 16 * 5];
    __shared__ float sC1[16 * 26];

    for (int i = tid; i < KK * HD; i += 128) sP[i] = g_pool[(size_t)g * KK * HD + i];
    for (int i = tid; i < 16 * HD * 5; i += 128) sw1[i] = cw1[i];
    for (int i = tid; i < 32 * 16 * 5; i += 128) sw2[i] = cw2[i];
    __syncthreads();

    for (int idx = tid; idx < 16 * 26; idx += 128) {
        int o = idx / 26, t = idx % 26;
        float acc = cb1[o];
#pragma unroll
        for (int j = 0; j < 5; j++)
#pragma unroll
            for (int c = 0; c < HD; c++)
                acc = fmaf(sP[(t + j) * HD + c], sw1[o * 160 + c * 5 + j], acc);
        sC1[o * 26 + t] = fmaxf(acc, 0.f);
    }
    __syncthreads();

    for (int idx = tid; idx < 32 * 22; idx += 128) {
        int o = idx / 22, t = idx % 22;
        float acc = cb2[o];
#pragma unroll
        for (int c = 0; c < 16; c++)
#pragma unroll
            for (int j = 0; j < 5; j++)
                acc = fmaf(sC1[c * 26 + t + j], sw2[o * 80 + c * 5 + j], acc);
        g_feat[(size_t)g * 704 + o * 22 + t] = fmaxf(acc, 0.f);
    }
}

// -------- fc head: 16 graphs per block, lw1 read once per 16 graphs --------
#define GPB 16
__global__ void k_fc(const float* __restrict__ lw1, const float* __restrict__ lb1,
                     const float* __restrict__ lw2, const float* __restrict__ lb2,
                     float* __restrict__ out) {
    __shared__ float sF[GPB * 704];   // 45KB
    __shared__ float sPart[GPB][4];
    int tid = threadIdx.x;  // 128
    int g0 = blockIdx.x * GPB;
    for (int i = tid; i < GPB * 704; i += 128) sF[i] = g_feat[(size_t)g0 * 704 + i];
    __syncthreads();
    float acc[GPB];
    float bb = lb1[tid];
#pragma unroll
    for (int g = 0; g < GPB; g++) acc[g] = bb;
    for (int i = 0; i < 704; i++) {
        float w = lw1[i * 128 + tid];
#pragma unroll
        for (int g = 0; g < GPB; g++) acc[g] = fmaf(sF[g * 704 + i], w, acc[g]);
    }
    float w2 = lw2[tid];
#pragma unroll
    for (int g = 0; g < GPB; g++) {
        float v = fmaxf(acc[g], 0.f) * w2;
#pragma unroll
        for (int o = 16; o; o >>= 1) v += __shfl_down_sync(0xffffffffu, v, o);
        if ((tid & 31) == 0) sPart[g][tid >> 5] = v;
    }
    __syncthreads();
    if (tid < GPB)
        out[g0 + tid] = sPart[tid][0] + sPart[tid][1] + sPart[tid][2] + sPart[tid][3] + lb2[0];
}

// -------- launch --------
extern "C" void kernel_launch(void* const* d_in, const int* in_sizes, int n_in,
                              void* d_out, int out_size) {
    const float* x = (const float*)d_in[0];
    const int* ei = (const int*)d_in[1];
    const int* batch = (const int*)d_in[2];
    int wi = 3;
    if (n_in > 3 && in_sizes[3] == 1) wi = 4;
    const float* W1  = (const float*)d_in[wi + 0];
    const float* b1  = (const float*)d_in[wi + 1];
    const float* W2  = (const float*)d_in[wi + 2];
    const float* b2  = (const float*)d_in[wi + 3];
    const float* W3  = (const float*)d_in[wi + 4];
    const float* b3  = (const float*)d_in[wi + 5];
    const float* cw1 = (const float*)d_in[wi + 6];
    const float* cb1 = (const float*)d_in[wi + 7];
    const float* cw2 = (const float*)d_in[wi + 8];
    const float* cb2 = (const float*)d_in[wi + 9];
    const float* lw1 = (const float*)d_in[wi + 10];
    const float* lb1 = (const float*)d_in[wi + 11];
    const float* lw2 = (const float*)d_in[wi + 12];
    const float* lb2 = (const float*)d_in[wi + 13];
    float* out = (float*)d_out;
    const int* src = ei;
    const int* dst = ei + EE;

    float *pA, *pB;
    cudaGetSymbolAddress((void**)&pA, g_bufA);
    cudaGetSymbolAddress((void**)&pB, g_bufB);

    k_init<<<(NN + 255) / 256, 256>>>();
    k_count<<<(EE + 255) / 256, 256>>>(dst);
    k_dis<<<(NN + 255) / 256, 256>>>();
    k_alloc<<<(NN + 255) / 256, 256>>>();
    k_scatter<<<(EE + 255) / 256, 256>>>(src, dst);
    k_starts<<<(GG + 256) / 256, 256>>>(batch);

    const int AGG_GRID = (NN + 31) / 32;
    // layer 1: Hlin1 = x@W1 -> B ; layer1 agg + relu + @W2 -> A (Hlin2)
    k_mm<9><<<(NN + 255) / 256, 256>>>(x, W1, pB);
    k_agg<true><<<AGG_GRID, 256>>>(pB, b1, W2, pA);
    // layer 2 agg + relu + @W3 -> B (Hlin3)
    k_agg<true><<<AGG_GRID, 256>>>(pA, b2, W3, pB);
    // layer 3 agg + relu -> A (H3)
    k_agg<false><<<AGG_GRID, 256>>>(pB, b3, nullptr, pA);

    k_sortpool<<<GG, 128>>>(pA);
    k_conv<<<GG, 128>>>(cw1, cb1, cw2, cb2);
    k_fc<<<GG / GPB, 128>>>(lw1, lb1, lw2, lb2, out);
}